// round 1
// baseline (speedup 1.0000x reference)
#include <cuda_runtime.h>
#include <math.h>

#define VOL (128*128*128)

// Accumulators (double): 0 reg_sumsq | 1-3 pair0 cross/gg/pp | 4-6 pair1 | 7-8 tv0 prod/sum | 9-10 tv1
__device__ double g_acc[12];

__global__ void init_kernel() {
    if (threadIdx.x < 12) g_acc[threadIdx.x] = 0.0;
}

__device__ __forceinline__ float warp_sum(float v) {
    #pragma unroll
    for (int o = 16; o > 0; o >>= 1) v += __shfl_xor_sync(0xffffffffu, v, o);
    return v;
}

// ---------------------------------------------------------------------------
// reg_field: sum((a-b)^2) over 12.58M floats
// ---------------------------------------------------------------------------
__global__ __launch_bounds__(256) void reg_kernel(const float4* __restrict__ a,
                                                  const float4* __restrict__ b, int n4) {
    float acc = 0.f;
    for (int i = blockIdx.x * blockDim.x + threadIdx.x; i < n4; i += gridDim.x * blockDim.x) {
        float4 x = a[i], y = b[i];
        float d0 = x.x - y.x, d1 = x.y - y.y, d2 = x.z - y.z, d3 = x.w - y.w;
        acc += d0 * d0 + d1 * d1 + d2 * d2 + d3 * d3;
    }
    __shared__ float s[8];
    float w = warp_sum(acc);
    if ((threadIdx.x & 31) == 0) s[threadIdx.x >> 5] = w;
    __syncthreads();
    if (threadIdx.x == 0) {
        float v = 0.f;
        #pragma unroll
        for (int k = 0; k < 8; k++) v += s[k];
        atomicAdd(&g_acc[0], (double)v);
    }
}

// ---------------------------------------------------------------------------
// tversky: both pairs in one pass. prod = sum(gt*pred), sumv = sum(gt+pred)
// ---------------------------------------------------------------------------
__global__ __launch_bounds__(256) void tversky_kernel(const float4* __restrict__ g0,
                                                      const float4* __restrict__ p0,
                                                      const float4* __restrict__ g1,
                                                      const float4* __restrict__ p1, int n4) {
    float pr0 = 0.f, sm0 = 0.f, pr1 = 0.f, sm1 = 0.f;
    for (int i = blockIdx.x * blockDim.x + threadIdx.x; i < n4; i += gridDim.x * blockDim.x) {
        float4 a = g0[i], b = p0[i];
        pr0 += a.x * b.x + a.y * b.y + a.z * b.z + a.w * b.w;
        sm0 += a.x + b.x + a.y + b.y + a.z + b.z + a.w + b.w;
        float4 c = g1[i], d = p1[i];
        pr1 += c.x * d.x + c.y * d.y + c.z * d.z + c.w * d.w;
        sm1 += c.x + d.x + c.y + d.y + c.z + d.z + c.w + d.w;
    }
    __shared__ float s[4][8];
    float v0 = warp_sum(pr0), v1 = warp_sum(sm0), v2 = warp_sum(pr1), v3 = warp_sum(sm1);
    int wid = threadIdx.x >> 5;
    if ((threadIdx.x & 31) == 0) { s[0][wid] = v0; s[1][wid] = v1; s[2][wid] = v2; s[3][wid] = v3; }
    __syncthreads();
    if (threadIdx.x == 0) {
        float t0 = 0, t1 = 0, t2 = 0, t3 = 0;
        #pragma unroll
        for (int k = 0; k < 8; k++) { t0 += s[0][k]; t1 += s[1][k]; t2 += s[2][k]; t3 += s[3][k]; }
        atomicAdd(&g_acc[7], (double)t0);
        atomicAdd(&g_acc[8], (double)t1);
        atomicAdd(&g_acc[9], (double)t2);
        atomicAdd(&g_acc[10], (double)t3);
    }
}

// ---------------------------------------------------------------------------
// LCC: fused 5x5x5 zero-padded box mean + deviation reductions
// Tile 32x8x8 output, halo 2. x-pass separable into sA; y/z window fused (25
// adds) at combine; d_gt kept in registers across the two phases.
// ---------------------------------------------------------------------------
#define TX 32
#define TY 8
#define TZ 8
#define HX 36
#define HY 12
#define HZ 12

__global__ __launch_bounds__(256) void lcc_kernel(const float* __restrict__ g0,
                                                  const float* __restrict__ p0,
                                                  const float* __restrict__ g1,
                                                  const float* __restrict__ p1) {
    __shared__ float sIn[HZ * HY * HX];  // 5184 floats
    __shared__ float sA[HZ * HY * TX];   // 4608 floats

    int blk = blockIdx.x;
    int pair = blk >> 11;
    int v = blk & 2047;
    int batch = v >> 10;
    int tile = v & 1023;
    int x0 = (tile & 3) * TX;
    int y0 = ((tile >> 2) & 15) * TY;
    int z0 = (tile >> 6) * TZ;

    const float* gt = (pair == 0 ? g0 : g1) + (size_t)batch * VOL;
    const float* pr = (pair == 0 ? p0 : p1) + (size_t)batch * VOL;

    int tid = threadIdx.x;
    float dg[8];
    float acc_cross = 0.f, acc_gg = 0.f, acc_pp = 0.f;

    #pragma unroll
    for (int phase = 0; phase < 2; phase++) {
        const float* src = phase ? pr : gt;

        // load halo tile with zero fill
        for (int i = tid; i < HZ * HY * HX; i += 256) {
            int lx = i % HX;
            int ly = (i / HX) % HY;
            int lz = i / (HX * HY);
            int gx = x0 + lx - 2, gy = y0 + ly - 2, gz = z0 + lz - 2;
            float val = 0.f;
            if ((unsigned)gx < 128u && (unsigned)gy < 128u && (unsigned)gz < 128u)
                val = src[((size_t)gz * 128 + gy) * 128 + gx];
            sIn[i] = val;
        }
        __syncthreads();

        // x-pass: 5-wide running sum along contiguous axis
        for (int i = tid; i < HZ * HY * TX; i += 256) {
            int lx = i % TX;
            int lyz = i / TX;  // combined (lz*HY + ly)
            const float* r = &sIn[lyz * HX + lx];
            sA[i] = r[0] + r[1] + r[2] + r[3] + r[4];
        }
        __syncthreads();

        // fused y/z 5x5 window + combine; 8 voxels per thread
        #pragma unroll
        for (int k = 0; k < 8; k++) {
            int i = tid + k * 256;
            int lx = i % TX;
            int ly = (i / TX) % TY;
            int lz = i / (TX * TY);
            float ws = 0.f;
            #pragma unroll
            for (int dz = 0; dz < 5; dz++) {
                #pragma unroll
                for (int dy = 0; dy < 5; dy++)
                    ws += sA[((lz + dz) * HY + (ly + dy)) * TX + lx];
            }
            float center = sIn[((lz + 2) * HY + (ly + 2)) * HX + lx + 2];
            float d = center - ws * (1.f / 125.f);
            if (phase == 0) {
                dg[k] = d;
                acc_gg += d * d;
            } else {
                acc_pp += d * d;
                acc_cross += dg[k] * d;
            }
        }
        __syncthreads();  // protect sIn/sA before next phase overwrites
    }

    // block reduction (reuse sA as scratch)
    float c = warp_sum(acc_cross);
    float gg = warp_sum(acc_gg);
    float pp = warp_sum(acc_pp);
    int wid = tid >> 5, lane = tid & 31;
    if (lane == 0) { sA[wid] = c; sA[8 + wid] = gg; sA[16 + wid] = pp; }
    __syncthreads();
    if (tid == 0) {
        float C = 0, G = 0, P = 0;
        #pragma unroll
        for (int w = 0; w < 8; w++) { C += sA[w]; G += sA[8 + w]; P += sA[16 + w]; }
        int base = 1 + pair * 3;
        atomicAdd(&g_acc[base + 0], (double)C);
        atomicAdd(&g_acc[base + 1], (double)G);
        atomicAdd(&g_acc[base + 2], (double)P);
    }
}

// ---------------------------------------------------------------------------
// finalize: combine scalars
// ---------------------------------------------------------------------------
__global__ void finalize_kernel(float* out) {
    const double omega_f = 2.0 * 3.0 * VOL;  // 12582912
    const double omega_i = 2.0 * 1.0 * VOL;  // 4194304

    double rf = sqrt(g_acc[0]) / omega_f;

    double num0 = g_acc[1] * g_acc[1];
    double den0 = g_acc[2] * g_acc[3];
    den0 = den0 > 1e-5 ? den0 : 1e-5;
    double lcc0 = -(num0 / den0) / omega_i;

    double num1 = g_acc[4] * g_acc[4];
    double den1 = g_acc[5] * g_acc[6];
    den1 = den1 > 1e-5 ? den1 : 1e-5;
    double lcc1 = -(num1 / den1) / omega_i;

    double s0 = g_acc[8] > 1e-5 ? g_acc[8] : 1e-5;
    double s1 = g_acc[10] > 1e-5 ? g_acc[10] : 1e-5;
    double tv0 = -g_acc[7] / s0;   // -0.5 * 2*prod / sum
    double tv1 = -g_acc[9] / s1;

    out[0] = (float)(rf + 10.0 * (lcc0 + lcc1) + 10.0 * (tv0 + tv1));
}

extern "C" void kernel_launch(void* const* d_in, const int* in_sizes, int n_in,
                              void* d_out, int out_size) {
    const float* F0  = (const float*)d_in[0];
    const float* F0g = (const float*)d_in[1];
    const float* I0  = (const float*)d_in[2];
    const float* I0R = (const float*)d_in[3];
    const float* I1  = (const float*)d_in[4];
    const float* I1R = (const float*)d_in[5];
    const float* S0  = (const float*)d_in[6];
    const float* S0g = (const float*)d_in[7];
    const float* S1  = (const float*)d_in[8];
    const float* S1g = (const float*)d_in[9];
    float* out = (float*)d_out;

    init_kernel<<<1, 32>>>();
    reg_kernel<<<2048, 256>>>((const float4*)F0, (const float4*)F0g, (2 * 3 * VOL) / 4);
    tversky_kernel<<<1024, 256>>>((const float4*)S0, (const float4*)S0g,
                                  (const float4*)S1, (const float4*)S1g, (2 * VOL) / 4);
    lcc_kernel<<<4096, 256>>>(I0, I0R, I1, I1R);
    finalize_kernel<<<1, 1>>>(out);
}

// round 2
// speedup vs baseline: 1.3161x; 1.3161x over previous
#include <cuda_runtime.h>
#include <math.h>

#define VOL (128*128*128)

// Accumulators (double): 0 reg_sumsq | 1-3 pair0 cross/gg/pp | 4-6 pair1 | 7-8 tv0 prod/sum | 9-10 tv1
__device__ double g_acc[12];

__global__ void init_kernel() {
    if (threadIdx.x < 12) g_acc[threadIdx.x] = 0.0;
}

__device__ __forceinline__ float warp_sum(float v) {
    #pragma unroll
    for (int o = 16; o > 0; o >>= 1) v += __shfl_xor_sync(0xffffffffu, v, o);
    return v;
}

// ---------------------------------------------------------------------------
// reg_field: sum((a-b)^2) over 12.58M floats
// ---------------------------------------------------------------------------
__global__ __launch_bounds__(256) void reg_kernel(const float4* __restrict__ a,
                                                  const float4* __restrict__ b, int n4) {
    float acc = 0.f;
    for (int i = blockIdx.x * blockDim.x + threadIdx.x; i < n4; i += gridDim.x * blockDim.x) {
        float4 x = a[i], y = b[i];
        float d0 = x.x - y.x, d1 = x.y - y.y, d2 = x.z - y.z, d3 = x.w - y.w;
        acc += d0 * d0 + d1 * d1 + d2 * d2 + d3 * d3;
    }
    __shared__ float s[8];
    float w = warp_sum(acc);
    if ((threadIdx.x & 31) == 0) s[threadIdx.x >> 5] = w;
    __syncthreads();
    if (threadIdx.x == 0) {
        float v = 0.f;
        #pragma unroll
        for (int k = 0; k < 8; k++) v += s[k];
        atomicAdd(&g_acc[0], (double)v);
    }
}

// ---------------------------------------------------------------------------
// tversky: both pairs in one pass. prod = sum(gt*pred), sumv = sum(gt+pred)
// ---------------------------------------------------------------------------
__global__ __launch_bounds__(256) void tversky_kernel(const float4* __restrict__ g0,
                                                      const float4* __restrict__ p0,
                                                      const float4* __restrict__ g1,
                                                      const float4* __restrict__ p1, int n4) {
    float pr0 = 0.f, sm0 = 0.f, pr1 = 0.f, sm1 = 0.f;
    for (int i = blockIdx.x * blockDim.x + threadIdx.x; i < n4; i += gridDim.x * blockDim.x) {
        float4 a = g0[i], b = p0[i];
        pr0 += a.x * b.x + a.y * b.y + a.z * b.z + a.w * b.w;
        sm0 += a.x + b.x + a.y + b.y + a.z + b.z + a.w + b.w;
        float4 c = g1[i], d = p1[i];
        pr1 += c.x * d.x + c.y * d.y + c.z * d.z + c.w * d.w;
        sm1 += c.x + d.x + c.y + d.y + c.z + d.z + c.w + d.w;
    }
    __shared__ float s[4][8];
    float v0 = warp_sum(pr0), v1 = warp_sum(sm0), v2 = warp_sum(pr1), v3 = warp_sum(sm1);
    int wid = threadIdx.x >> 5;
    if ((threadIdx.x & 31) == 0) { s[0][wid] = v0; s[1][wid] = v1; s[2][wid] = v2; s[3][wid] = v3; }
    __syncthreads();
    if (threadIdx.x == 0) {
        float t0 = 0, t1 = 0, t2 = 0, t3 = 0;
        #pragma unroll
        for (int k = 0; k < 8; k++) { t0 += s[0][k]; t1 += s[1][k]; t2 += s[2][k]; t3 += s[3][k]; }
        atomicAdd(&g_acc[7], (double)t0);
        atomicAdd(&g_acc[8], (double)t1);
        atomicAdd(&g_acc[9], (double)t2);
        atomicAdd(&g_acc[10], (double)t3);
    }
}

// ---------------------------------------------------------------------------
// LCC: z-marching sliding-window separable 5x5x5 box filter, both inputs in
// one pass. Tile 32(x) x 8(y) x 32(z), halo 2. Thread = fixed (lx,ly) role;
// x-pass and y-pass in SMEM per slice, z-pass in a 5-deep register ring.
// Full unroll makes ring indices and SMEM offsets compile-time constants.
// ---------------------------------------------------------------------------
#define TX 32
#define TY 8
#define TZ 32
#define HX 36
#define HY 12
#define NSLICE (TZ + 4)
#define SLICE_ELEMS (HY * HX)   // 432
#define XS_ELEMS (HY * TX)      // 384

__global__ __launch_bounds__(256) void lcc_kernel(const float* __restrict__ g0,
                                                  const float* __restrict__ p0,
                                                  const float* __restrict__ g1,
                                                  const float* __restrict__ p1) {
    __shared__ float rawG[SLICE_ELEMS], rawP[SLICE_ELEMS];
    __shared__ float xsG[XS_ELEMS], xsP[XS_ELEMS];

    int blk = blockIdx.x;
    int x0 = (blk & 3) * TX;
    int y0 = ((blk >> 2) & 15) * TY;
    int z0 = ((blk >> 6) & 3) * TZ;
    int batch = (blk >> 8) & 1;
    int pair = blk >> 9;

    const float* gt = (pair == 0 ? g0 : g1) + (size_t)batch * VOL;
    const float* pr = (pair == 0 ? p0 : p1) + (size_t)batch * VOL;

    int tid = threadIdx.x;
    int lx = tid & 31, ly = tid >> 5;

    // ---- load roles (computed once; slice loop only adds constant z offsets)
    int e0 = tid, e1 = tid + 256;
    int l0y = e0 / HX, l0x = e0 - l0y * HX;
    int l1y = e1 / HX, l1x = e1 - l1y * HX;
    int gx0 = x0 + l0x - 2, gy0 = y0 + l0y - 2;
    int gx1 = x0 + l1x - 2, gy1 = y0 + l1y - 2;
    bool hasE1 = (e1 < SLICE_ELEMS);
    bool v0 = ((unsigned)gx0 < 128u) & ((unsigned)gy0 < 128u);
    bool v1 = hasE1 & ((unsigned)gx1 < 128u) & ((unsigned)gy1 < 128u);
    int zbase = z0 - 2;
    // base pointers at slice zbase for each role (offset 0 when invalid; load predicated off)
    size_t zb = (size_t)zbase * (128 * 128);
    const float* pg0 = gt + (v0 ? (gy0 * 128 + gx0) : 0) + zb;
    const float* pp0 = pr + (v0 ? (gy0 * 128 + gx0) : 0) + zb;
    const float* pg1 = gt + (v1 ? (gy1 * 128 + gx1) : 0) + zb;
    const float* pp1 = pr + (v1 ? (gy1 * 128 + gx1) : 0) + zb;

    bool hasF1 = (tid < XS_ELEMS - 256);  // tid < 128

    // register rings: xy box sums and raw centers, depth 5
    float bg[5], bp[5], cg[5], cp[5];
    #pragma unroll
    for (int k = 0; k < 5; k++) { bg[k] = bp[k] = cg[k] = cp[k] = 0.f; }

    float accC = 0.f, accG = 0.f, accP = 0.f;

    #pragma unroll
    for (int zi = 0; zi < NSLICE; zi++) {
        bool zv = (unsigned)(zbase + zi) < 128u;
        const int zo = zi * (128 * 128);  // compile-time constant per unrolled iter

        // stage 1: load raw slices (both inputs), predicated zero fill
        rawG[e0] = (v0 && zv) ? pg0[zo] : 0.f;
        rawP[e0] = (v0 && zv) ? pp0[zo] : 0.f;
        if (hasE1) {
            rawG[e1] = (v1 && zv) ? pg1[zo] : 0.f;
            rawP[e1] = (v1 && zv) ? pp1[zo] : 0.f;
        }
        __syncthreads();

        // stage 2: x-pass (5-wide) into xs; capture raw center into ring
        {
            const float* r = &rawG[ly * HX + lx];
            xsG[tid] = r[0] + r[1] + r[2] + r[3] + r[4];
            const float* q = &rawP[ly * HX + lx];
            xsP[tid] = q[0] + q[1] + q[2] + q[3] + q[4];
            if (hasF1) {
                const float* r2 = &rawG[(8 + ly) * HX + lx];
                xsG[tid + 256] = r2[0] + r2[1] + r2[2] + r2[3] + r2[4];
                const float* q2 = &rawP[(8 + ly) * HX + lx];
                xsP[tid + 256] = q2[0] + q2[1] + q2[2] + q2[3] + q2[4];
            }
            cg[zi % 5] = rawG[(ly + 2) * HX + lx + 2];
            cp[zi % 5] = rawP[(ly + 2) * HX + lx + 2];
        }
        __syncthreads();

        // stage 3: y-pass (5-wide) from xs into register ring; z-pass in regs
        float xyg = 0.f, xyp = 0.f;
        #pragma unroll
        for (int dy = 0; dy < 5; dy++) {
            xyg += xsG[(ly + dy) * TX + lx];
            xyp += xsP[(ly + dy) * TX + lx];
        }
        bg[zi % 5] = xyg;
        bp[zi % 5] = xyp;

        if (zi >= 4) {
            float sg = bg[0] + bg[1] + bg[2] + bg[3] + bg[4];
            float sp = bp[0] + bp[1] + bp[2] + bp[3] + bp[4];
            float dgv = cg[(zi - 2) % 5] - sg * (1.f / 125.f);
            float dpv = cp[(zi - 2) % 5] - sp * (1.f / 125.f);
            accG += dgv * dgv;
            accP += dpv * dpv;
            accC += dgv * dpv;
        }
    }

    // block reduction (reuse xsG as scratch)
    float c = warp_sum(accC);
    float gg = warp_sum(accG);
    float pp = warp_sum(accP);
    int wid = tid >> 5, lane = tid & 31;
    if (lane == 0) { xsG[wid] = c; xsG[8 + wid] = gg; xsG[16 + wid] = pp; }
    __syncthreads();
    if (tid == 0) {
        float C = 0, G = 0, P = 0;
        #pragma unroll
        for (int w = 0; w < 8; w++) { C += xsG[w]; G += xsG[8 + w]; P += xsG[16 + w]; }
        int base = 1 + pair * 3;
        atomicAdd(&g_acc[base + 0], (double)C);
        atomicAdd(&g_acc[base + 1], (double)G);
        atomicAdd(&g_acc[base + 2], (double)P);
    }
}

// ---------------------------------------------------------------------------
// finalize: combine scalars
// ---------------------------------------------------------------------------
__global__ void finalize_kernel(float* out) {
    const double omega_f = 2.0 * 3.0 * VOL;  // 12582912
    const double omega_i = 2.0 * 1.0 * VOL;  // 4194304

    double rf = sqrt(g_acc[0]) / omega_f;

    double num0 = g_acc[1] * g_acc[1];
    double den0 = g_acc[2] * g_acc[3];
    den0 = den0 > 1e-5 ? den0 : 1e-5;
    double lcc0 = -(num0 / den0) / omega_i;

    double num1 = g_acc[4] * g_acc[4];
    double den1 = g_acc[5] * g_acc[6];
    den1 = den1 > 1e-5 ? den1 : 1e-5;
    double lcc1 = -(num1 / den1) / omega_i;

    double s0 = g_acc[8] > 1e-5 ? g_acc[8] : 1e-5;
    double s1 = g_acc[10] > 1e-5 ? g_acc[10] : 1e-5;
    double tv0 = -g_acc[7] / s0;   // -0.5 * 2*prod / sum
    double tv1 = -g_acc[9] / s1;

    out[0] = (float)(rf + 10.0 * (lcc0 + lcc1) + 10.0 * (tv0 + tv1));
}

extern "C" void kernel_launch(void* const* d_in, const int* in_sizes, int n_in,
                              void* d_out, int out_size) {
    const float* F0  = (const float*)d_in[0];
    const float* F0g = (const float*)d_in[1];
    const float* I0  = (const float*)d_in[2];
    const float* I0R = (const float*)d_in[3];
    const float* I1  = (const float*)d_in[4];
    const float* I1R = (const float*)d_in[5];
    const float* S0  = (const float*)d_in[6];
    const float* S0g = (const float*)d_in[7];
    const float* S1  = (const float*)d_in[8];
    const float* S1g = (const float*)d_in[9];
    float* out = (float*)d_out;

    init_kernel<<<1, 32>>>();
    reg_kernel<<<2048, 256>>>((const float4*)F0, (const float4*)F0g, (2 * 3 * VOL) / 4);
    tversky_kernel<<<1024, 256>>>((const float4*)S0, (const float4*)S0g,
                                  (const float4*)S1, (const float4*)S1g, (2 * VOL) / 4);
    lcc_kernel<<<1024, 256>>>(I0, I0R, I1, I1R);
    finalize_kernel<<<1, 1>>>(out);
}

// round 4
// speedup vs baseline: 2.1871x; 1.6618x over previous
#include <cuda_runtime.h>
#include <math.h>

#define VOL (128*128*128)

// Accumulators (double): 0 reg_sumsq | 1-3 pair0 cross/gg/pp | 4-6 pair1 | 7-8 tv0 prod/sum | 9-10 tv1
__device__ double g_acc[12];

__global__ void init_kernel() {
    if (threadIdx.x < 12) g_acc[threadIdx.x] = 0.0;
}

__device__ __forceinline__ float warp_sum(float v) {
    #pragma unroll
    for (int o = 16; o > 0; o >>= 1) v += __shfl_xor_sync(0xffffffffu, v, o);
    return v;
}

// ---------------------------------------------------------------------------
// Fused kernel: blocks [0,1024) lcc | [1024,1536) reg_field | [1536,1792) tversky
// ---------------------------------------------------------------------------
#define TX 32
#define TY 8
#define TZ 32
#define HX 36
#define HY 12
#define NSLICE (TZ + 4)
#define SLICE_ELEMS (HY * HX)   // 432
#define XS_ELEMS (HY * TX)      // 384

#define LCC_BLOCKS 1024
#define REG_BLOCKS 512
#define TV_BLOCKS  256

__global__ __launch_bounds__(256) void fused_kernel(
    const float* __restrict__ F0, const float* __restrict__ F0g,
    const float* __restrict__ I0, const float* __restrict__ I0R,
    const float* __restrict__ I1, const float* __restrict__ I1R,
    const float* __restrict__ S0, const float* __restrict__ S0g,
    const float* __restrict__ S1, const float* __restrict__ S1g) {

    // SMEM: lcc double-buffered float2 {gt, pred}; streaming branches reuse as scratch
    __shared__ float2 raw[2][SLICE_ELEMS];
    __shared__ float2 xs[2][XS_ELEMS];

    int blk = blockIdx.x;
    int tid = threadIdx.x;

    if (blk < LCC_BLOCKS) {
        // ================= LCC: pipelined z-march, 1 sync/slice =================
        int x0 = (blk & 3) * TX;
        int y0 = ((blk >> 2) & 15) * TY;
        int z0 = ((blk >> 6) & 3) * TZ;
        int batch = (blk >> 8) & 1;
        int pair = blk >> 9;

        const float* gt = (pair == 0 ? I0 : I1) + (size_t)batch * VOL;
        const float* pr = (pair == 0 ? I0R : I1R) + (size_t)batch * VOL;

        int lx = tid & 31, ly = tid >> 5;

        // load roles
        int e0 = tid, e1 = tid + 256;
        int l0y = e0 / HX, l0x = e0 - l0y * HX;
        int l1y = e1 / HX, l1x = e1 - l1y * HX;
        int gx0 = x0 + l0x - 2, gy0 = y0 + l0y - 2;
        int gx1 = x0 + l1x - 2, gy1 = y0 + l1y - 2;
        bool hasE1 = (e1 < SLICE_ELEMS);  // tid < 176
        bool v0 = ((unsigned)gx0 < 128u) & ((unsigned)gy0 < 128u);
        bool v1 = hasE1 & ((unsigned)gx1 < 128u) & ((unsigned)gy1 < 128u);
        int zbase = z0 - 2;
        size_t zb = (size_t)zbase * (128 * 128);
        const float* pg0 = gt + (v0 ? (gy0 * 128 + gx0) : 0) + zb;
        const float* pp0 = pr + (v0 ? (gy0 * 128 + gx0) : 0) + zb;
        const float* pg1 = gt + (v1 ? (gy1 * 128 + gx1) : 0) + zb;
        const float* pp1 = pr + (v1 ? (gy1 * 128 + gx1) : 0) + zb;

        bool hasF1 = (tid < XS_ELEMS - 256);  // tid < 128

        // prologue: slice 0
        {
            bool zv = (unsigned)(zbase) < 128u;
            float a = 0.f, b = 0.f, c = 0.f, d = 0.f;
            if (v0 & zv) { a = pg0[0]; b = pp0[0]; }
            if (v1 & zv) { c = pg1[0]; d = pp1[0]; }
            raw[0][e0] = make_float2(a, b);
            if (hasE1) raw[0][e1] = make_float2(c, d);
        }
        __syncthreads();

        float2 bgp[5], cgp[5];
        #pragma unroll
        for (int k = 0; k < 5; k++) { bgp[k] = make_float2(0.f, 0.f); cgp[k] = make_float2(0.f, 0.f); }
        float accC = 0.f, accG = 0.f, accP = 0.f;

        #pragma unroll
        for (int zi = 0; zi < NSLICE; zi++) {
            const int cur = zi & 1, nxt = cur ^ 1;

            // prefetch slice zi+1 into registers (overlaps x-pass)
            float ng0 = 0.f, np0 = 0.f, ng1 = 0.f, np1 = 0.f;
            if (zi + 1 < NSLICE) {
                bool zv = (unsigned)(zbase + zi + 1) < 128u;
                const int zo = (zi + 1) * (128 * 128);
                if (v0 & zv) { ng0 = pg0[zo]; np0 = pp0[zo]; }
                if (v1 & zv) { ng1 = pg1[zo]; np1 = pp1[zo]; }
            }

            // x-pass: 5-wide from raw[cur] into xs[cur]; capture center
            {
                const float2* r = &raw[cur][ly * HX + lx];
                float2 s;
                s.x = r[0].x + r[1].x + r[2].x + r[3].x + r[4].x;
                s.y = r[0].y + r[1].y + r[2].y + r[3].y + r[4].y;
                xs[cur][tid] = s;
                if (hasF1) {
                    const float2* r2 = &raw[cur][(8 + ly) * HX + lx];
                    float2 s2;
                    s2.x = r2[0].x + r2[1].x + r2[2].x + r2[3].x + r2[4].x;
                    s2.y = r2[0].y + r2[1].y + r2[2].y + r2[3].y + r2[4].y;
                    xs[cur][tid + 256] = s2;
                }
                cgp[zi % 5] = raw[cur][(ly + 2) * HX + lx + 2];
            }

            // stage prefetched slice into raw[nxt]
            raw[nxt][e0] = make_float2(ng0, np0);
            if (hasE1) raw[nxt][e1] = make_float2(ng1, np1);
            __syncthreads();

            // y-pass from xs[cur]; z-pass in register ring
            {
                const float2* q = &xs[cur][ly * TX + lx];
                float2 w;
                w.x = q[0].x + q[TX].x + q[2 * TX].x + q[3 * TX].x + q[4 * TX].x;
                w.y = q[0].y + q[TX].y + q[2 * TX].y + q[3 * TX].y + q[4 * TX].y;
                bgp[zi % 5] = w;
            }

            if (zi >= 4) {
                float sg = bgp[0].x + bgp[1].x + bgp[2].x + bgp[3].x + bgp[4].x;
                float sp = bgp[0].y + bgp[1].y + bgp[2].y + bgp[3].y + bgp[4].y;
                float2 c = cgp[(zi - 2) % 5];
                float dgv = c.x - sg * (1.f / 125.f);
                float dpv = c.y - sp * (1.f / 125.f);
                accG += dgv * dgv;
                accP += dpv * dpv;
                accC += dgv * dpv;
            }
        }

        // block reduction (reuse xs as scratch)
        float* scr = (float*)&xs[0][0];
        float c = warp_sum(accC);
        float gg = warp_sum(accG);
        float pp = warp_sum(accP);
        int wid = tid >> 5, lane = tid & 31;
        __syncthreads();
        if (lane == 0) { scr[wid] = c; scr[8 + wid] = gg; scr[16 + wid] = pp; }
        __syncthreads();
        if (tid == 0) {
            float C = 0, G = 0, P = 0;
            #pragma unroll
            for (int w = 0; w < 8; w++) { C += scr[w]; G += scr[8 + w]; P += scr[16 + w]; }
            int base = 1 + pair * 3;
            atomicAdd(&g_acc[base + 0], (double)C);
            atomicAdd(&g_acc[base + 1], (double)G);
            atomicAdd(&g_acc[base + 2], (double)P);
        }
    } else if (blk < LCC_BLOCKS + REG_BLOCKS) {
        // ================= reg_field: sum((a-b)^2) =================
        const float4* a = (const float4*)F0;
        const float4* b = (const float4*)F0g;
        const int n4 = (2 * 3 * VOL) / 4;
        int bid = blk - LCC_BLOCKS;
        float acc = 0.f;
        for (int i = bid * 256 + tid; i < n4; i += REG_BLOCKS * 256) {
            float4 x = a[i], y = b[i];
            float d0 = x.x - y.x, d1 = x.y - y.y, d2 = x.z - y.z, d3 = x.w - y.w;
            acc += d0 * d0 + d1 * d1 + d2 * d2 + d3 * d3;
        }
        float* scr = (float*)&xs[0][0];
        float w = warp_sum(acc);
        if ((tid & 31) == 0) scr[tid >> 5] = w;
        __syncthreads();
        if (tid == 0) {
            float v = 0.f;
            #pragma unroll
            for (int k = 0; k < 8; k++) v += scr[k];
            atomicAdd(&g_acc[0], (double)v);
        }
    } else {
        // ================= tversky: both pairs =================
        const float4* g0 = (const float4*)S0;
        const float4* p0 = (const float4*)S0g;
        const float4* g1 = (const float4*)S1;
        const float4* p1 = (const float4*)S1g;
        const int n4 = (2 * VOL) / 4;
        int bid = blk - LCC_BLOCKS - REG_BLOCKS;
        float pr0 = 0.f, sm0 = 0.f, pr1 = 0.f, sm1 = 0.f;
        for (int i = bid * 256 + tid; i < n4; i += TV_BLOCKS * 256) {
            float4 a = g0[i], b = p0[i];
            pr0 += a.x * b.x + a.y * b.y + a.z * b.z + a.w * b.w;
            sm0 += a.x + b.x + a.y + b.y + a.z + b.z + a.w + b.w;
            float4 cc = g1[i], dd = p1[i];
            pr1 += cc.x * dd.x + cc.y * dd.y + cc.z * dd.z + cc.w * dd.w;
            sm1 += cc.x + dd.x + cc.y + dd.y + cc.z + dd.z + cc.w + dd.w;
        }
        float* scr = (float*)&xs[0][0];
        float v0 = warp_sum(pr0), v1 = warp_sum(sm0), v2 = warp_sum(pr1), v3 = warp_sum(sm1);
        int wid = tid >> 5;
        if ((tid & 31) == 0) { scr[wid] = v0; scr[8 + wid] = v1; scr[16 + wid] = v2; scr[24 + wid] = v3; }
        __syncthreads();
        if (tid == 0) {
            float t0 = 0, t1 = 0, t2 = 0, t3 = 0;
            #pragma unroll
            for (int k = 0; k < 8; k++) { t0 += scr[k]; t1 += scr[8 + k]; t2 += scr[16 + k]; t3 += scr[24 + k]; }
            atomicAdd(&g_acc[7], (double)t0);
            atomicAdd(&g_acc[8], (double)t1);
            atomicAdd(&g_acc[9], (double)t2);
            atomicAdd(&g_acc[10], (double)t3);
        }
    }
}

// ---------------------------------------------------------------------------
// finalize: combine scalars
// ---------------------------------------------------------------------------
__global__ void finalize_kernel(float* out) {
    const double omega_f = 2.0 * 3.0 * VOL;  // 12582912
    const double omega_i = 2.0 * 1.0 * VOL;  // 4194304

    double rf = sqrt(g_acc[0]) / omega_f;

    double num0 = g_acc[1] * g_acc[1];
    double den0 = g_acc[2] * g_acc[3];
    den0 = den0 > 1e-5 ? den0 : 1e-5;
    double lcc0 = -(num0 / den0) / omega_i;

    double num1 = g_acc[4] * g_acc[4];
    double den1 = g_acc[5] * g_acc[6];
    den1 = den1 > 1e-5 ? den1 : 1e-5;
    double lcc1 = -(num1 / den1) / omega_i;

    double s0 = g_acc[8] > 1e-5 ? g_acc[8] : 1e-5;
    double s1 = g_acc[10] > 1e-5 ? g_acc[10] : 1e-5;
    double tv0 = -g_acc[7] / s0;   // -0.5 * 2*prod / sum
    double tv1 = -g_acc[9] / s1;

    out[0] = (float)(rf + 10.0 * (lcc0 + lcc1) + 10.0 * (tv0 + tv1));
}

extern "C" void kernel_launch(void* const* d_in, const int* in_sizes, int n_in,
                              void* d_out, int out_size) {
    const float* F0  = (const float*)d_in[0];
    const float* F0g = (const float*)d_in[1];
    const float* I0  = (const float*)d_in[2];
    const float* I0R = (const float*)d_in[3];
    const float* I1  = (const float*)d_in[4];
    const float* I1R = (const float*)d_in[5];
    const float* S0  = (const float*)d_in[6];
    const float* S0g = (const float*)d_in[7];
    const float* S1  = (const float*)d_in[8];
    const float* S1g = (const float*)d_in[9];
    float* out = (float*)d_out;

    init_kernel<<<1, 32>>>();
    fused_kernel<<<LCC_BLOCKS + REG_BLOCKS + TV_BLOCKS, 256>>>(
        F0, F0g, I0, I0R, I1, I1R, S0, S0g, S1, S1g);
    finalize_kernel<<<1, 1>>>(out);
}